// round 2
// baseline (speedup 1.0000x reference)
#include <cuda_runtime.h>

#define NN 100000
#define EE 3200000
#define HH 32
#define LL 4
#define GG 1000
#define CC 2
#define BN_EPS 1e-5f

#define FUSED_BLOCKS 1184          // 8 * 148 SMs
#define SCAN_B 98                  // ceil(100000 / 1024)

// ---------------- scratch (static device globals; no allocation) -------------
__device__ float g_h[NN * HH];          // node features (post-activation)
__device__ float g_z[NN * HH];          // pre-BN MLP output
__device__ int   g_deg[NN];
__device__ int   g_rowptr[NN + 1];
__device__ int   g_cursor[NN];
__device__ int   g_csrc[EE];            // CSR-by-dst: source node per slot
__device__ int   g_blksum[SCAN_B];
__device__ float g_pooled[GG * HH];
__device__ float g_psum[FUSED_BLOCKS * HH];
__device__ float g_psq [FUSED_BLOCKS * HH];
__device__ float g_bn_a[HH];
__device__ float g_bn_b[HH];

// ---------------- init: zero deg + pooled ------------------------------------
__global__ void zero_kernel() {
    int i = blockIdx.x * blockDim.x + threadIdx.x;
    if (i < NN) g_deg[i] = 0;
    if (i < GG * HH) g_pooled[i] = 0.0f;
}

// ---------------- encoder: h = x @ W_enc + b_enc (F_IN = 1) ------------------
__global__ void encoder_kernel(const float* __restrict__ x,
                               const float* __restrict__ W_enc,
                               const float* __restrict__ b_enc) {
    int idx = blockIdx.x * blockDim.x + threadIdx.x;
    if (idx >= NN * HH) return;
    int i = idx >> 5;
    int k = idx & 31;
    g_h[idx] = fmaf(x[i], W_enc[k], b_enc[k]);
}

// ---------------- CSR build --------------------------------------------------
__global__ void hist_kernel(const int* __restrict__ ei) {
    int e = blockIdx.x * blockDim.x + threadIdx.x;
    if (e >= EE) return;
    int d = ei[EE + e];                 // dst
    atomicAdd(&g_deg[d], 1);
}

__global__ void scan1_kernel() {
    __shared__ int sm[1024];
    int t = threadIdx.x;
    int idx = blockIdx.x * 1024 + t;
    int v = (idx < NN) ? g_deg[idx] : 0;
    sm[t] = v;
    __syncthreads();
    #pragma unroll
    for (int off = 1; off < 1024; off <<= 1) {
        int tmp = (t >= off) ? sm[t - off] : 0;
        __syncthreads();
        sm[t] += tmp;
        __syncthreads();
    }
    if (idx < NN) g_rowptr[idx] = sm[t] - v;   // exclusive
    if (t == 1023) g_blksum[blockIdx.x] = sm[t];
}

__global__ void scan2_kernel() {
    if (threadIdx.x == 0) {
        int run = 0;
        for (int i = 0; i < SCAN_B; i++) { int tv = g_blksum[i]; g_blksum[i] = run; run += tv; }
        g_rowptr[NN] = run;             // == EE
    }
}

__global__ void scan3_kernel() {
    int idx = blockIdx.x * 1024 + threadIdx.x;
    if (idx >= NN) return;
    int v = g_rowptr[idx] + g_blksum[blockIdx.x];
    g_rowptr[idx] = v;
    g_cursor[idx] = v;
}

__global__ void fill_kernel(const int* __restrict__ ei) {
    int e = blockIdx.x * blockDim.x + threadIdx.x;
    if (e >= EE) return;
    int s = ei[e];
    int d = ei[EE + e];
    int p = atomicAdd(&g_cursor[d], 1);
    g_csrc[p] = s;
}

// ---------------- fused layer: gather + GIN + 2-layer MLP + BN partials ------
// Warp per node, lane = channel (H = 32).
__global__ void __launch_bounds__(256)
fused_layer_kernel(const float* __restrict__ eps,
                   const float* __restrict__ W1, const float* __restrict__ b1,
                   const float* __restrict__ W2, const float* __restrict__ b2,
                   int l) {
    __shared__ float W1s[HH * HH], W2s[HH * HH];
    __shared__ float b1s[HH], b2s[HH];
    __shared__ float redS[8][HH], redQ[8][HH];

    int t = threadIdx.x;
    const float* W1l = W1 + l * HH * HH;
    const float* W2l = W2 + l * HH * HH;
    #pragma unroll
    for (int i = t; i < HH * HH; i += 256) { W1s[i] = W1l[i]; W2s[i] = W2l[i]; }
    if (t < HH) { b1s[t] = b1[l * HH + t]; b2s[t] = b2[l * HH + t]; }
    __syncthreads();

    const float eps1 = 1.0f + eps[l];
    int lane = t & 31;
    int w = t >> 5;
    int gwarp = blockIdx.x * 8 + w;
    int nwarps = FUSED_BLOCKS * 8;

    float wsum = 0.0f, wsq = 0.0f;

    for (int i = gwarp; i < NN; i += nwarps) {
        int rs = g_rowptr[i];
        int re = g_rowptr[i + 1];
        float acc = 0.0f;
        for (int base = rs; base < re; base += 32) {
            int e = base + lane;
            int s = (e < re) ? g_csrc[e] : 0;
            int cnt = re - base; if (cnt > 32) cnt = 32;
            #pragma unroll
            for (int j = 0; j < 32; ++j) {
                int sj = __shfl_sync(0xffffffffu, s, j);
                if (j < cnt) acc += g_h[sj * HH + lane];
            }
        }
        float tv = fmaf(eps1, g_h[i * HH + lane], acc);

        // z1 = relu(t @ W1 + b1): lane k computes channel k
        float z1 = b1s[lane];
        #pragma unroll
        for (int j = 0; j < 32; ++j)
            z1 = fmaf(__shfl_sync(0xffffffffu, tv, j), W1s[j * HH + lane], z1);
        z1 = fmaxf(z1, 0.0f);

        // z2 = z1 @ W2 + b2
        float z2 = b2s[lane];
        #pragma unroll
        for (int j = 0; j < 32; ++j)
            z2 = fmaf(__shfl_sync(0xffffffffu, z1, j), W2s[j * HH + lane], z2);

        g_z[i * HH + lane] = z2;
        wsum += z2;
        wsq  = fmaf(z2, z2, wsq);
    }

    // block-level BN partial reduction (no global atomics)
    redS[w][lane] = wsum;
    redQ[w][lane] = wsq;
    __syncthreads();
    if (w == 0) {
        float s = redS[0][lane], q = redQ[0][lane];
        #pragma unroll
        for (int r = 1; r < 8; ++r) { s += redS[r][lane]; q += redQ[r][lane]; }
        g_psum[blockIdx.x * HH + lane] = s;
        g_psq [blockIdx.x * HH + lane] = q;
    }
}

// ---------------- BN finalize: fold into affine a*z + b ----------------------
__global__ void bn_finalize_kernel(const float* __restrict__ gamma,
                                   const float* __restrict__ beta, int l) {
    int k = threadIdx.x & 31;
    int r = threadIdx.x >> 5;       // 8 groups
    float s = 0.0f, q = 0.0f;
    for (int b = r; b < FUSED_BLOCKS; b += 8) {
        s += g_psum[b * HH + k];
        q += g_psq [b * HH + k];
    }
    __shared__ float ss[8][HH], qq[8][HH];
    ss[r][k] = s; qq[r][k] = q;
    __syncthreads();
    if (r == 0) {
        #pragma unroll
        for (int i = 1; i < 8; ++i) { s += ss[i][k]; q += qq[i][k]; }
        float mu  = s * (1.0f / (float)NN);
        float var = q * (1.0f / (float)NN) - mu * mu;
        float inv = rsqrtf(var + BN_EPS);
        float a = gamma[l * HH + k] * inv;
        g_bn_a[k] = a;
        g_bn_b[k] = fmaf(-mu, a, beta[l * HH + k]);
    }
}

// ---------------- BN apply + ReLU (+ pooling on last layer) ------------------
__global__ void bn_apply_kernel(const int* __restrict__ batch, int do_pool) {
    int idx = blockIdx.x * blockDim.x + threadIdx.x;
    if (idx >= NN * HH) return;
    int k = idx & 31;
    float v = fmaf(g_bn_a[k], g_z[idx], g_bn_b[k]);
    v = fmaxf(v, 0.0f);
    g_h[idx] = v;
    if (do_pool) {
        int g = batch[idx >> 5];
        atomicAdd(&g_pooled[g * HH + k], v);
    }
}

// ---------------- classifier -------------------------------------------------
__global__ void classifier_kernel(const float* __restrict__ W_cls,
                                  const float* __restrict__ b_cls,
                                  float* __restrict__ out) {
    int g = blockIdx.x * blockDim.x + threadIdx.x;
    if (g >= GG) return;
    float c0 = b_cls[0], c1 = b_cls[1];
    #pragma unroll
    for (int k = 0; k < HH; ++k) {
        float p = g_pooled[g * HH + k];
        c0 = fmaf(p, W_cls[k * CC + 0], c0);
        c1 = fmaf(p, W_cls[k * CC + 1], c1);
    }
    out[g * CC + 0] = c0;
    out[g * CC + 1] = c1;
}

// -----------------------------------------------------------------------------
extern "C" void kernel_launch(void* const* d_in, const int* in_sizes, int n_in,
                              void* d_out, int out_size) {
    const float* x     = (const float*)d_in[0];
    const int*   ei    = (const int*)  d_in[1];
    const int*   batch = (const int*)  d_in[2];
    const float* W_enc = (const float*)d_in[3];
    const float* b_enc = (const float*)d_in[4];
    const float* eps   = (const float*)d_in[5];
    const float* W1    = (const float*)d_in[6];
    const float* b1    = (const float*)d_in[7];
    const float* W2    = (const float*)d_in[8];
    const float* b2    = (const float*)d_in[9];
    const float* gamma = (const float*)d_in[10];
    const float* beta  = (const float*)d_in[11];
    const float* W_cls = (const float*)d_in[12];
    const float* b_cls = (const float*)d_in[13];
    float* out = (float*)d_out;

    zero_kernel<<<(NN + 255) / 256, 256>>>();
    encoder_kernel<<<(NN * HH + 255) / 256, 256>>>(x, W_enc, b_enc);

    hist_kernel<<<(EE + 255) / 256, 256>>>(ei);
    scan1_kernel<<<SCAN_B, 1024>>>();
    scan2_kernel<<<1, 32>>>();
    scan3_kernel<<<SCAN_B, 1024>>>();
    fill_kernel<<<(EE + 255) / 256, 256>>>(ei);

    for (int l = 0; l < LL; ++l) {
        fused_layer_kernel<<<FUSED_BLOCKS, 256>>>(eps, W1, b1, W2, b2, l);
        bn_finalize_kernel<<<1, 256>>>(gamma, beta, l);
        bn_apply_kernel<<<(NN * HH + 255) / 256, 256>>>(batch, l == LL - 1 ? 1 : 0);
    }

    classifier_kernel<<<(GG + 127) / 128, 128>>>(W_cls, b_cls, out);
}

// round 4
// speedup vs baseline: 1.4719x; 1.4719x over previous
#include <cuda_runtime.h>

#define NN 100000
#define EE 3200000
#define HH 32
#define LL 4
#define GG 1000
#define CC 2
#define BN_EPS 1e-5f

#define FUSED_BLOCKS 1184          // 8 * 148 SMs
#define SCAN_B 98                  // ceil(100000 / 1024)

// ---------------- scratch (static device globals; no allocation) -------------
__device__ float g_h[NN * HH];          // node features (post-activation)
__device__ float g_z[NN * HH];          // pre-BN MLP output
__device__ int   g_deg[NN];
__device__ int   g_rowptr[NN + 1];
__device__ int   g_cursor[NN];
__device__ int   g_csrc[EE];            // CSR-by-dst: source node per slot
__device__ int   g_blksum[SCAN_B];
__device__ float g_pooled[GG * HH];
__device__ float g_psum[FUSED_BLOCKS * HH];
__device__ float g_psq [FUSED_BLOCKS * HH];
__device__ float g_bn_a[HH];
__device__ float g_bn_b[HH];

// ---------------- init: zero deg + pooled ------------------------------------
__global__ void zero_kernel() {
    int i = blockIdx.x * blockDim.x + threadIdx.x;
    if (i < NN) g_deg[i] = 0;
    if (i < GG * HH) g_pooled[i] = 0.0f;
}

// ---------------- encoder: h = x @ W_enc + b_enc (F_IN = 1) ------------------
__global__ void encoder_kernel(const float* __restrict__ x,
                               const float* __restrict__ W_enc,
                               const float* __restrict__ b_enc) {
    int idx = blockIdx.x * blockDim.x + threadIdx.x;
    if (idx >= NN * HH) return;
    int i = idx >> 5;
    int k = idx & 31;
    g_h[idx] = fmaf(x[i], W_enc[k], b_enc[k]);
}

// ---------------- CSR build --------------------------------------------------
__global__ void hist_kernel(const int* __restrict__ ei) {
    int e = blockIdx.x * blockDim.x + threadIdx.x;
    if (e >= EE) return;
    int d = ei[EE + e];                 // dst
    atomicAdd(&g_deg[d], 1);
}

__global__ void scan1_kernel() {
    __shared__ int sm[1024];
    int t = threadIdx.x;
    int idx = blockIdx.x * 1024 + t;
    int v = (idx < NN) ? g_deg[idx] : 0;
    sm[t] = v;
    __syncthreads();
    #pragma unroll
    for (int off = 1; off < 1024; off <<= 1) {
        int tmp = (t >= off) ? sm[t - off] : 0;
        __syncthreads();
        sm[t] += tmp;
        __syncthreads();
    }
    if (idx < NN) g_rowptr[idx] = sm[t] - v;   // exclusive
    if (t == 1023) g_blksum[blockIdx.x] = sm[t];
}

__global__ void scan2_kernel() {
    if (threadIdx.x == 0) {
        int run = 0;
        for (int i = 0; i < SCAN_B; i++) { int tv = g_blksum[i]; g_blksum[i] = run; run += tv; }
        g_rowptr[NN] = run;             // == EE
    }
}

__global__ void scan3_kernel() {
    int idx = blockIdx.x * 1024 + threadIdx.x;
    if (idx >= NN) return;
    int v = g_rowptr[idx] + g_blksum[blockIdx.x];
    g_rowptr[idx] = v;
    g_cursor[idx] = v;
}

__global__ void fill_kernel(const int* __restrict__ ei) {
    int e = blockIdx.x * blockDim.x + threadIdx.x;
    if (e >= EE) return;
    int s = ei[e];
    int d = ei[EE + e];
    int p = atomicAdd(&g_cursor[d], 1);
    g_csrc[p] = s;
}

// ---------------- fused layer: gather + GIN + 2-layer MLP + BN partials ------
// Warp processes 4 consecutive nodes. group g = lane>>3 owns node quad*4+g;
// sub = lane&7 owns channels [sub*4, sub*4+4) as a float4.
__global__ void __launch_bounds__(256)
fused_layer_kernel(const float* __restrict__ eps,
                   const float* __restrict__ W1, const float* __restrict__ b1,
                   const float* __restrict__ W2, const float* __restrict__ b2,
                   int l) {
    __shared__ float W1s[HH * HH], W2s[HH * HH];
    __shared__ float b1s[HH], b2s[HH];
    __shared__ float4 redS[8][32], redQ[8][32];

    int t = threadIdx.x;
    const float* W1l = W1 + l * HH * HH;
    const float* W2l = W2 + l * HH * HH;
    #pragma unroll
    for (int i = t; i < HH * HH; i += 256) { W1s[i] = W1l[i]; W2s[i] = W2l[i]; }
    if (t < HH) { b1s[t] = b1[l * HH + t]; b2s[t] = b2[l * HH + t]; }
    __syncthreads();

    const float eps1 = 1.0f + eps[l];
    const int lane = t & 31;
    const int w = t >> 5;
    const int g = lane >> 3;
    const int sub = lane & 7;
    const unsigned FULL = 0xffffffffu;

    int gw = blockIdx.x * 8 + w;
    int nquads = NN / 4;                 // 25000
    int nw = FUSED_BLOCKS * 8;

    float4 wsum = make_float4(0.f, 0.f, 0.f, 0.f);
    float4 wsq  = make_float4(0.f, 0.f, 0.f, 0.f);

    for (int q = gw; q < nquads; q += nw) {
        int i = q * 4 + g;
        int rs = g_rowptr[i];
        int re = g_rowptr[i + 1];
        int deg = re - rs;
        int maxdeg = __reduce_max_sync(FULL, deg);

        // self term
        float4 self = *(const float4*)(g_h + i * HH + sub * 4);
        float4 acc;
        acc.x = eps1 * self.x; acc.y = eps1 * self.y;
        acc.z = eps1 * self.z; acc.w = eps1 * self.w;

        // gather neighbors: 8 edges per group per chunk
        int chunks = (maxdeg + 7) >> 3;
        for (int c = 0; c < chunks; ++c) {
            int base = rs + c * 8;
            int e = base + sub;
            int s = (e < re) ? __ldg(&g_csrc[e]) : 0;
            int cnt = re - base;            // may be <=0 for this group
            #pragma unroll
            for (int r = 0; r < 8; ++r) {
                int sj = __shfl_sync(FULL, s, g * 8 + r);
                if (r < cnt) {
                    const float4 v = *(const float4*)(g_h + sj * HH + sub * 4);
                    acc.x += v.x; acc.y += v.y; acc.z += v.z; acc.w += v.w;
                }
            }
        }

        // ---- MLP layer 1: z1 = relu(acc @ W1 + b1), 4 nodes batched ----
        float4 z1;
        z1.x = b1s[sub * 4 + 0]; z1.y = b1s[sub * 4 + 1];
        z1.z = b1s[sub * 4 + 2]; z1.w = b1s[sub * 4 + 3];
        #pragma unroll
        for (int r = 0; r < 8; ++r) {
            float bx = __shfl_sync(FULL, acc.x, g * 8 + r);  // tv[4r+0]
            float by = __shfl_sync(FULL, acc.y, g * 8 + r);  // tv[4r+1]
            float bz = __shfl_sync(FULL, acc.z, g * 8 + r);  // tv[4r+2]
            float bw = __shfl_sync(FULL, acc.w, g * 8 + r);  // tv[4r+3]
            const float4 w0 = *(const float4*)&W1s[(4 * r + 0) * HH + sub * 4];
            const float4 w1 = *(const float4*)&W1s[(4 * r + 1) * HH + sub * 4];
            const float4 w2 = *(const float4*)&W1s[(4 * r + 2) * HH + sub * 4];
            const float4 w3 = *(const float4*)&W1s[(4 * r + 3) * HH + sub * 4];
            z1.x = fmaf(bx, w0.x, z1.x); z1.x = fmaf(by, w1.x, z1.x);
            z1.x = fmaf(bz, w2.x, z1.x); z1.x = fmaf(bw, w3.x, z1.x);
            z1.y = fmaf(bx, w0.y, z1.y); z1.y = fmaf(by, w1.y, z1.y);
            z1.y = fmaf(bz, w2.y, z1.y); z1.y = fmaf(bw, w3.y, z1.y);
            z1.z = fmaf(bx, w0.z, z1.z); z1.z = fmaf(by, w1.z, z1.z);
            z1.z = fmaf(bz, w2.z, z1.z); z1.z = fmaf(bw, w3.z, z1.z);
            z1.w = fmaf(bx, w0.w, z1.w); z1.w = fmaf(by, w1.w, z1.w);
            z1.w = fmaf(bz, w2.w, z1.w); z1.w = fmaf(bw, w3.w, z1.w);
        }
        z1.x = fmaxf(z1.x, 0.f); z1.y = fmaxf(z1.y, 0.f);
        z1.z = fmaxf(z1.z, 0.f); z1.w = fmaxf(z1.w, 0.f);

        // ---- MLP layer 2: z2 = z1 @ W2 + b2 ----
        float4 z2;
        z2.x = b2s[sub * 4 + 0]; z2.y = b2s[sub * 4 + 1];
        z2.z = b2s[sub * 4 + 2]; z2.w = b2s[sub * 4 + 3];
        #pragma unroll
        for (int r = 0; r < 8; ++r) {
            float bx = __shfl_sync(FULL, z1.x, g * 8 + r);
            float by = __shfl_sync(FULL, z1.y, g * 8 + r);
            float bz = __shfl_sync(FULL, z1.z, g * 8 + r);
            float bw = __shfl_sync(FULL, z1.w, g * 8 + r);
            const float4 w0 = *(const float4*)&W2s[(4 * r + 0) * HH + sub * 4];
            const float4 w1 = *(const float4*)&W2s[(4 * r + 1) * HH + sub * 4];
            const float4 w2 = *(const float4*)&W2s[(4 * r + 2) * HH + sub * 4];
            const float4 w3 = *(const float4*)&W2s[(4 * r + 3) * HH + sub * 4];
            z2.x = fmaf(bx, w0.x, z2.x); z2.x = fmaf(by, w1.x, z2.x);
            z2.x = fmaf(bz, w2.x, z2.x); z2.x = fmaf(bw, w3.x, z2.x);
            z2.y = fmaf(bx, w0.y, z2.y); z2.y = fmaf(by, w1.y, z2.y);
            z2.y = fmaf(bz, w2.y, z2.y); z2.y = fmaf(bw, w3.y, z2.y);
            z2.z = fmaf(bx, w0.z, z2.z); z2.z = fmaf(by, w1.z, z2.z);
            z2.z = fmaf(bz, w2.z, z2.z); z2.z = fmaf(bw, w3.z, z2.z);
            z2.w = fmaf(bx, w0.w, z2.w); z2.w = fmaf(by, w1.w, z2.w);
            z2.w = fmaf(bz, w2.w, z2.w); z2.w = fmaf(bw, w3.w, z2.w);
        }

        *(float4*)(g_z + i * HH + sub * 4) = z2;
        wsum.x += z2.x; wsum.y += z2.y; wsum.z += z2.z; wsum.w += z2.w;
        wsq.x = fmaf(z2.x, z2.x, wsq.x); wsq.y = fmaf(z2.y, z2.y, wsq.y);
        wsq.z = fmaf(z2.z, z2.z, wsq.z); wsq.w = fmaf(z2.w, z2.w, wsq.w);
    }

    // block-level BN partial reduction
    redS[w][lane] = wsum;
    redQ[w][lane] = wsq;
    __syncthreads();
    if (w == 0) {
        float4 s = redS[0][lane], qv = redQ[0][lane];
        #pragma unroll
        for (int r = 1; r < 8; ++r) {
            float4 a = redS[r][lane], b = redQ[r][lane];
            s.x += a.x; s.y += a.y; s.z += a.z; s.w += a.w;
            qv.x += b.x; qv.y += b.y; qv.z += b.z; qv.w += b.w;
        }
        // reduce across the 4 groups (lanes differing in bits 3,4)
        #pragma unroll
        for (int m = 8; m < 32; m <<= 1) {
            s.x += __shfl_xor_sync(FULL, s.x, m);
            s.y += __shfl_xor_sync(FULL, s.y, m);
            s.z += __shfl_xor_sync(FULL, s.z, m);
            s.w += __shfl_xor_sync(FULL, s.w, m);
            qv.x += __shfl_xor_sync(FULL, qv.x, m);
            qv.y += __shfl_xor_sync(FULL, qv.y, m);
            qv.z += __shfl_xor_sync(FULL, qv.z, m);
            qv.w += __shfl_xor_sync(FULL, qv.w, m);
        }
        if (g == 0) {
            *(float4*)&g_psum[blockIdx.x * HH + sub * 4] = s;
            *(float4*)&g_psq [blockIdx.x * HH + sub * 4] = qv;
        }
    }
}

// ---------------- BN finalize: fold into affine a*z + b ----------------------
__global__ void bn_finalize_kernel(const float* __restrict__ gamma,
                                   const float* __restrict__ beta, int l) {
    int k = threadIdx.x & 31;
    int r = threadIdx.x >> 5;       // 8 groups
    float s = 0.0f, q = 0.0f;
    for (int b = r; b < FUSED_BLOCKS; b += 8) {
        s += g_psum[b * HH + k];
        q += g_psq [b * HH + k];
    }
    __shared__ float ss[8][HH], qq[8][HH];
    ss[r][k] = s; qq[r][k] = q;
    __syncthreads();
    if (r == 0) {
        #pragma unroll
        for (int i = 1; i < 8; ++i) { s += ss[i][k]; q += qq[i][k]; }
        float mu  = s * (1.0f / (float)NN);
        float var = q * (1.0f / (float)NN) - mu * mu;
        float inv = rsqrtf(var + BN_EPS);
        float a = gamma[l * HH + k] * inv;
        g_bn_a[k] = a;
        g_bn_b[k] = fmaf(-mu, a, beta[l * HH + k]);
    }
}

// ---------------- BN apply + ReLU (+ pooling on last layer) ------------------
__global__ void bn_apply_kernel(const int* __restrict__ batch, int do_pool) {
    int idx = blockIdx.x * blockDim.x + threadIdx.x;   // float4 index
    if (idx >= NN * 8) return;
    int sub = idx & 7;
    float4 z = *(const float4*)(g_z + idx * 4);
    float4 a = *(const float4*)&g_bn_a[sub * 4];
    float4 b = *(const float4*)&g_bn_b[sub * 4];
    float4 v;
    v.x = fmaxf(fmaf(a.x, z.x, b.x), 0.f);
    v.y = fmaxf(fmaf(a.y, z.y, b.y), 0.f);
    v.z = fmaxf(fmaf(a.z, z.z, b.z), 0.f);
    v.w = fmaxf(fmaf(a.w, z.w, b.w), 0.f);
    *(float4*)(g_h + idx * 4) = v;
    if (do_pool) {
        int gidx = batch[idx >> 3];
        float* p = &g_pooled[gidx * HH + sub * 4];
        atomicAdd(p + 0, v.x);
        atomicAdd(p + 1, v.y);
        atomicAdd(p + 2, v.z);
        atomicAdd(p + 3, v.w);
    }
}

// ---------------- classifier -------------------------------------------------
__global__ void classifier_kernel(const float* __restrict__ W_cls,
                                  const float* __restrict__ b_cls,
                                  float* __restrict__ out) {
    int g = blockIdx.x * blockDim.x + threadIdx.x;
    if (g >= GG) return;
    float c0 = b_cls[0], c1 = b_cls[1];
    #pragma unroll
    for (int k = 0; k < HH; ++k) {
        float p = g_pooled[g * HH + k];
        c0 = fmaf(p, W_cls[k * CC + 0], c0);
        c1 = fmaf(p, W_cls[k * CC + 1], c1);
    }
    out[g * CC + 0] = c0;
    out[g * CC + 1] = c1;
}

// -----------------------------------------------------------------------------
extern "C" void kernel_launch(void* const* d_in, const int* in_sizes, int n_in,
                              void* d_out, int out_size) {
    const float* x     = (const float*)d_in[0];
    const int*   ei    = (const int*)  d_in[1];
    const int*   batch = (const int*)  d_in[2];
    const float* W_enc = (const float*)d_in[3];
    const float* b_enc = (const float*)d_in[4];
    const float* eps   = (const float*)d_in[5];
    const float* W1    = (const float*)d_in[6];
    const float* b1    = (const float*)d_in[7];
    const float* W2    = (const float*)d_in[8];
    const float* b2    = (const float*)d_in[9];
    const float* gamma = (const float*)d_in[10];
    const float* beta  = (const float*)d_in[11];
    const float* W_cls = (const float*)d_in[12];
    const float* b_cls = (const float*)d_in[13];
    float* out = (float*)d_out;

    zero_kernel<<<(NN + 255) / 256, 256>>>();
    encoder_kernel<<<(NN * HH + 255) / 256, 256>>>(x, W_enc, b_enc);

    hist_kernel<<<(EE + 255) / 256, 256>>>(ei);
    scan1_kernel<<<SCAN_B, 1024>>>();
    scan2_kernel<<<1, 32>>>();
    scan3_kernel<<<SCAN_B, 1024>>>();
    fill_kernel<<<(EE + 255) / 256, 256>>>(ei);

    for (int l = 0; l < LL; ++l) {
        fused_layer_kernel<<<FUSED_BLOCKS, 256>>>(eps, W1, b1, W2, b2, l);
        bn_finalize_kernel<<<1, 256>>>(gamma, beta, l);
        bn_apply_kernel<<<(NN * 8 + 255) / 256, 256>>>(batch, l == LL - 1 ? 1 : 0);
    }

    classifier_kernel<<<(GG + 127) / 128, 128>>>(W_cls, b_cls, out);
}

// round 9
// speedup vs baseline: 1.5549x; 1.0564x over previous
#include <cuda_runtime.h>
#include <cuda_fp16.h>

#define NN 100000
#define EE 3200000
#define HH 32
#define LL 4
#define GG 1000
#define CC 2
#define BN_EPS 1e-5f

#define FUSED_BLOCKS 1184          // 8 * 148 SMs
#define SCAN_B 98                  // ceil(100000 / 1024)

// ---------------- scratch (static device globals; no allocation) -------------
__device__ __half g_hh[NN * HH];        // node features (post-activation), fp16
__device__ float  g_z[NN * HH];         // pre-BN MLP output, fp32
__device__ int    g_deg[NN];
__device__ int    g_rowptr[NN + 1];
__device__ int    g_cursor[NN];
__device__ int    g_csrc[EE];           // CSR-by-dst: source node per slot
__device__ int    g_blksum[SCAN_B];
__device__ float  g_pooled[GG * HH];
__device__ float  g_psum[FUSED_BLOCKS * HH];
__device__ float  g_psq [FUSED_BLOCKS * HH];
__device__ float  g_bn_a[HH];
__device__ float  g_bn_b[HH];

// ---------------- init: zero deg + pooled ------------------------------------
__global__ void zero_kernel() {
    int i = blockIdx.x * blockDim.x + threadIdx.x;
    if (i < NN) g_deg[i] = 0;
    if (i < GG * HH) g_pooled[i] = 0.0f;
}

// ---------------- encoder: h = x @ W_enc + b_enc (F_IN = 1), fp16 out --------
__global__ void encoder_kernel(const float* __restrict__ x,
                               const float* __restrict__ W_enc,
                               const float* __restrict__ b_enc) {
    int idx = blockIdx.x * blockDim.x + threadIdx.x;   // half2 index
    if (idx >= NN * 16) return;
    int i = idx >> 4;
    int k2 = idx & 15;                                  // channel pair
    float xv = x[i];
    float v0 = fmaf(xv, W_enc[2 * k2 + 0], b_enc[2 * k2 + 0]);
    float v1 = fmaf(xv, W_enc[2 * k2 + 1], b_enc[2 * k2 + 1]);
    *(__half2*)(g_hh + idx * 2) = __floats2half2_rn(v0, v1);
}

// ---------------- CSR build --------------------------------------------------
__global__ void hist_kernel(const int* __restrict__ ei) {
    int e = blockIdx.x * blockDim.x + threadIdx.x;
    if (e >= EE) return;
    int d = ei[EE + e];                 // dst
    atomicAdd(&g_deg[d], 1);
}

__global__ void scan1_kernel() {
    __shared__ int sm[1024];
    int t = threadIdx.x;
    int idx = blockIdx.x * 1024 + t;
    int v = (idx < NN) ? g_deg[idx] : 0;
    sm[t] = v;
    __syncthreads();
    #pragma unroll
    for (int off = 1; off < 1024; off <<= 1) {
        int tmp = (t >= off) ? sm[t - off] : 0;
        __syncthreads();
        sm[t] += tmp;
        __syncthreads();
    }
    if (idx < NN) g_rowptr[idx] = sm[t] - v;   // exclusive
    if (t == 1023) g_blksum[blockIdx.x] = sm[t];
}

__global__ void scan2_kernel() {
    if (threadIdx.x == 0) {
        int run = 0;
        for (int i = 0; i < SCAN_B; i++) { int tv = g_blksum[i]; g_blksum[i] = run; run += tv; }
        g_rowptr[NN] = run;             // == EE
    }
}

__global__ void scan3_kernel() {
    int idx = blockIdx.x * 1024 + threadIdx.x;
    if (idx >= NN) return;
    int v = g_rowptr[idx] + g_blksum[blockIdx.x];
    g_rowptr[idx] = v;
    g_cursor[idx] = v;
}

__global__ void fill_kernel(const int* __restrict__ ei) {
    int e = blockIdx.x * blockDim.x + threadIdx.x;
    if (e >= EE) return;
    int s = ei[e];
    int d = ei[EE + e];
    int p = atomicAdd(&g_cursor[d], 1);
    g_csrc[p] = s;
}

// ---------------- fused layer: gather + GIN + 2-layer MLP + BN partials ------
// Warp processes 4 consecutive nodes. group g = lane>>3 owns node quad*4+g;
// sub = lane&7 owns channels [sub*4, sub*4+4). h rows are fp16 (64B), each
// sub lane loads one uint2 (= 2 half2 = 4 channels).
__global__ void __launch_bounds__(256)
fused_layer_kernel(const float* __restrict__ eps,
                   const float* __restrict__ W1, const float* __restrict__ b1,
                   const float* __restrict__ W2, const float* __restrict__ b2,
                   int l) {
    __shared__ float W1s[HH * HH], W2s[HH * HH];
    __shared__ float b1s[HH], b2s[HH];
    __shared__ float4 redS[8][32], redQ[8][32];

    int t = threadIdx.x;
    const float* W1l = W1 + l * HH * HH;
    const float* W2l = W2 + l * HH * HH;
    #pragma unroll
    for (int i = t; i < HH * HH; i += 256) { W1s[i] = W1l[i]; W2s[i] = W2l[i]; }
    if (t < HH) { b1s[t] = b1[l * HH + t]; b2s[t] = b2[l * HH + t]; }
    __syncthreads();

    const float eps1 = 1.0f + eps[l];
    const int lane = t & 31;
    const int w = t >> 5;
    const int g = lane >> 3;
    const int sub = lane & 7;
    const unsigned FULL = 0xffffffffu;

    const uint2* __restrict__ hrows = (const uint2*)g_hh;  // 8 uint2 per row

    int gw = blockIdx.x * 8 + w;
    int nquads = NN / 4;                 // 25000
    int nw = FUSED_BLOCKS * 8;

    float4 wsum = make_float4(0.f, 0.f, 0.f, 0.f);
    float4 wsq  = make_float4(0.f, 0.f, 0.f, 0.f);

    for (int q = gw; q < nquads; q += nw) {
        int i = q * 4 + g;
        int rs = g_rowptr[i];
        int re = g_rowptr[i + 1];
        int deg = re - rs;
        int maxdeg = __reduce_max_sync(FULL, deg);

        // self term
        uint2 raw = hrows[i * 8 + sub];
        float2 s01 = __half22float2(*(const __half2*)&raw.x);
        float2 s23 = __half22float2(*(const __half2*)&raw.y);
        float4 acc;
        acc.x = eps1 * s01.x; acc.y = eps1 * s01.y;
        acc.z = eps1 * s23.x; acc.w = eps1 * s23.y;

        // gather neighbors: 8 edges per group per chunk
        int chunks = (maxdeg + 7) >> 3;
        for (int c = 0; c < chunks; ++c) {
            int base = rs + c * 8;
            int e = base + sub;
            int s = (e < re) ? __ldg(&g_csrc[e]) : 0;
            int cnt = re - base;            // may be <=0 for this group
            #pragma unroll
            for (int r = 0; r < 8; ++r) {
                int sj = __shfl_sync(FULL, s, g * 8 + r);
                if (r < cnt) {
                    uint2 nb = hrows[sj * 8 + sub];
                    float2 f01 = __half22float2(*(const __half2*)&nb.x);
                    float2 f23 = __half22float2(*(const __half2*)&nb.y);
                    acc.x += f01.x; acc.y += f01.y;
                    acc.z += f23.x; acc.w += f23.y;
                }
            }
        }

        // ---- MLP layer 1: z1 = relu(acc @ W1 + b1), 4 nodes batched ----
        float4 z1;
        z1.x = b1s[sub * 4 + 0]; z1.y = b1s[sub * 4 + 1];
        z1.z = b1s[sub * 4 + 2]; z1.w = b1s[sub * 4 + 3];
        #pragma unroll
        for (int r = 0; r < 8; ++r) {
            float bx = __shfl_sync(FULL, acc.x, g * 8 + r);  // tv[4r+0]
            float by = __shfl_sync(FULL, acc.y, g * 8 + r);  // tv[4r+1]
            float bz = __shfl_sync(FULL, acc.z, g * 8 + r);  // tv[4r+2]
            float bw = __shfl_sync(FULL, acc.w, g * 8 + r);  // tv[4r+3]
            const float4 w0 = *(const float4*)&W1s[(4 * r + 0) * HH + sub * 4];
            const float4 w1 = *(const float4*)&W1s[(4 * r + 1) * HH + sub * 4];
            const float4 w2 = *(const float4*)&W1s[(4 * r + 2) * HH + sub * 4];
            const float4 w3 = *(const float4*)&W1s[(4 * r + 3) * HH + sub * 4];
            z1.x = fmaf(bx, w0.x, z1.x); z1.x = fmaf(by, w1.x, z1.x);
            z1.x = fmaf(bz, w2.x, z1.x); z1.x = fmaf(bw, w3.x, z1.x);
            z1.y = fmaf(bx, w0.y, z1.y); z1.y = fmaf(by, w1.y, z1.y);
            z1.y = fmaf(bz, w2.y, z1.y); z1.y = fmaf(bw, w3.y, z1.y);
            z1.z = fmaf(bx, w0.z, z1.z); z1.z = fmaf(by, w1.z, z1.z);
            z1.z = fmaf(bz, w2.z, z1.z); z1.z = fmaf(bw, w3.z, z1.z);
            z1.w = fmaf(bx, w0.w, z1.w); z1.w = fmaf(by, w1.w, z1.w);
            z1.w = fmaf(bz, w2.w, z1.w); z1.w = fmaf(bw, w3.w, z1.w);
        }
        z1.x = fmaxf(z1.x, 0.f); z1.y = fmaxf(z1.y, 0.f);
        z1.z = fmaxf(z1.z, 0.f); z1.w = fmaxf(z1.w, 0.f);

        // ---- MLP layer 2: z2 = z1 @ W2 + b2 ----
        float4 z2;
        z2.x = b2s[sub * 4 + 0]; z2.y = b2s[sub * 4 + 1];
        z2.z = b2s[sub * 4 + 2]; z2.w = b2s[sub * 4 + 3];
        #pragma unroll
        for (int r = 0; r < 8; ++r) {
            float bx = __shfl_sync(FULL, z1.x, g * 8 + r);
            float by = __shfl_sync(FULL, z1.y, g * 8 + r);
            float bz = __shfl_sync(FULL, z1.z, g * 8 + r);
            float bw = __shfl_sync(FULL, z1.w, g * 8 + r);
            const float4 w0 = *(const float4*)&W2s[(4 * r + 0) * HH + sub * 4];
            const float4 w1 = *(const float4*)&W2s[(4 * r + 1) * HH + sub * 4];
            const float4 w2 = *(const float4*)&W2s[(4 * r + 2) * HH + sub * 4];
            const float4 w3 = *(const float4*)&W2s[(4 * r + 3) * HH + sub * 4];
            z2.x = fmaf(bx, w0.x, z2.x); z2.x = fmaf(by, w1.x, z2.x);
            z2.x = fmaf(bz, w2.x, z2.x); z2.x = fmaf(bw, w3.x, z2.x);
            z2.y = fmaf(bx, w0.y, z2.y); z2.y = fmaf(by, w1.y, z2.y);
            z2.y = fmaf(bz, w2.y, z2.y); z2.y = fmaf(bw, w3.y, z2.y);
            z2.z = fmaf(bx, w0.z, z2.z); z2.z = fmaf(by, w1.z, z2.z);
            z2.z = fmaf(bz, w2.z, z2.z); z2.z = fmaf(bw, w3.z, z2.z);
            z2.w = fmaf(bx, w0.w, z2.w); z2.w = fmaf(by, w1.w, z2.w);
            z2.w = fmaf(bz, w2.w, z2.w); z2.w = fmaf(bw, w3.w, z2.w);
        }

        *(float4*)(g_z + i * HH + sub * 4) = z2;
        wsum.x += z2.x; wsum.y += z2.y; wsum.z += z2.z; wsum.w += z2.w;
        wsq.x = fmaf(z2.x, z2.x, wsq.x); wsq.y = fmaf(z2.y, z2.y, wsq.y);
        wsq.z = fmaf(z2.z, z2.z, wsq.z); wsq.w = fmaf(z2.w, z2.w, wsq.w);
    }

    // block-level BN partial reduction
    redS[w][lane] = wsum;
    redQ[w][lane] = wsq;
    __syncthreads();
    if (w == 0) {
        float4 s = redS[0][lane], qv = redQ[0][lane];
        #pragma unroll
        for (int r = 1; r < 8; ++r) {
            float4 a = redS[r][lane], b = redQ[r][lane];
            s.x += a.x; s.y += a.y; s.z += a.z; s.w += a.w;
            qv.x += b.x; qv.y += b.y; qv.z += b.z; qv.w += b.w;
        }
        // reduce across the 4 groups (lanes differing in bits 3,4)
        #pragma unroll
        for (int m = 8; m < 32; m <<= 1) {
            s.x += __shfl_xor_sync(FULL, s.x, m);
            s.y += __shfl_xor_sync(FULL, s.y, m);
            s.z += __shfl_xor_sync(FULL, s.z, m);
            s.w += __shfl_xor_sync(FULL, s.w, m);
            qv.x += __shfl_xor_sync(FULL, qv.x, m);
            qv.y += __shfl_xor_sync(FULL, qv.y, m);
            qv.z += __shfl_xor_sync(FULL, qv.z, m);
            qv.w += __shfl_xor_sync(FULL, qv.w, m);
        }
        if (g == 0) {
            *(float4*)&g_psum[blockIdx.x * HH + sub * 4] = s;
            *(float4*)&g_psq [blockIdx.x * HH + sub * 4] = qv;
        }
    }
}

// ---------------- BN finalize: fold into affine a*z + b ----------------------
__global__ void bn_finalize_kernel(const float* __restrict__ gamma,
                                   const float* __restrict__ beta, int l) {
    int k = threadIdx.x & 31;
    int r = threadIdx.x >> 5;       // 8 groups
    float s = 0.0f, q = 0.0f;
    for (int b = r; b < FUSED_BLOCKS; b += 8) {
        s += g_psum[b * HH + k];
        q += g_psq [b * HH + k];
    }
    __shared__ float ss[8][HH], qq[8][HH];
    ss[r][k] = s; qq[r][k] = q;
    __syncthreads();
    if (r == 0) {
        #pragma unroll
        for (int i = 1; i < 8; ++i) { s += ss[i][k]; q += qq[i][k]; }
        float mu  = s * (1.0f / (float)NN);
        float var = q * (1.0f / (float)NN) - mu * mu;
        float inv = rsqrtf(var + BN_EPS);
        float a = gamma[l * HH + k] * inv;
        g_bn_a[k] = a;
        g_bn_b[k] = fmaf(-mu, a, beta[l * HH + k]);
    }
}

// ---------------- BN apply + ReLU (+ pooling on last layer), fp16 h out ------
__global__ void bn_apply_kernel(const int* __restrict__ batch, int do_pool) {
    int idx = blockIdx.x * blockDim.x + threadIdx.x;   // float4 / uint2 index
    if (idx >= NN * 8) return;
    int sub = idx & 7;
    float4 z = *(const float4*)(g_z + idx * 4);
    float4 a = *(const float4*)&g_bn_a[sub * 4];
    float4 b = *(const float4*)&g_bn_b[sub * 4];
    float4 v;
    v.x = fmaxf(fmaf(a.x, z.x, b.x), 0.f);
    v.y = fmaxf(fmaf(a.y, z.y, b.y), 0.f);
    v.z = fmaxf(fmaf(a.z, z.z, b.z), 0.f);
    v.w = fmaxf(fmaf(a.w, z.w, b.w), 0.f);
    uint2 packed;
    *(__half2*)&packed.x = __floats2half2_rn(v.x, v.y);
    *(__half2*)&packed.y = __floats2half2_rn(v.z, v.w);
    ((uint2*)g_hh)[idx] = packed;
    if (do_pool) {
        int gidx = batch[idx >> 3];
        float* p = &g_pooled[gidx * HH + sub * 4];
        atomicAdd(p + 0, v.x);
        atomicAdd(p + 1, v.y);
        atomicAdd(p + 2, v.z);
        atomicAdd(p + 3, v.w);
    }
}

// ---------------- classifier -------------------------------------------------
__global__ void classifier_kernel(const float* __restrict__ W_cls,
                                  const float* __restrict__ b_cls,
                                  float* __restrict__ out) {
    int g = blockIdx.x * blockDim.x + threadIdx.x;
    if (g >= GG) return;
    float c0 = b_cls[0], c1 = b_cls[1];
    #pragma unroll
    for (int k = 0; k < HH; ++k) {
        float p = g_pooled[g * HH + k];
        c0 = fmaf(p, W_cls[k * CC + 0], c0);
        c1 = fmaf(p, W_cls[k * CC + 1], c1);
    }
    out[g * CC + 0] = c0;
    out[g * CC + 1] = c1;
}

// -----------------------------------------------------------------------------
extern "C" void kernel_launch(void* const* d_in, const int* in_sizes, int n_in,
                              void* d_out, int out_size) {
    const float* x     = (const float*)d_in[0];
    const int*   ei    = (const int*)  d_in[1];
    const int*   batch = (const int*)  d_in[2];
    const float* W_enc = (const float*)d_in[3];
    const float* b_enc = (const float*)d_in[4];
    const float* eps   = (const float*)d_in[5];
    const float* W1    = (const float*)d_in[6];
    const float* b1    = (const float*)d_in[7];
    const float* W2    = (const float*)d_in[8];
    const float* b2    = (const float*)d_in[9];
    const float* gamma = (const float*)d_in[10];
    const float* beta  = (const float*)d_in[11];
    const float* W_cls = (const float*)d_in[12];
    const float* b_cls = (const float*)d_in[13];
    float* out = (float*)d_out;

    zero_kernel<<<(NN + 255) / 256, 256>>>();
    encoder_kernel<<<(NN * 16 + 255) / 256, 256>>>(x, W_enc, b_enc);

    hist_kernel<<<(EE + 255) / 256, 256>>>(ei);
    scan1_kernel<<<SCAN_B, 1024>>>();
    scan2_kernel<<<1, 32>>>();
    scan3_kernel<<<SCAN_B, 1024>>>();
    fill_kernel<<<(EE + 255) / 256, 256>>>(ei);

    for (int l = 0; l < LL; ++l) {
        fused_layer_kernel<<<FUSED_BLOCKS, 256>>>(eps, W1, b1, W2, b2, l);
        bn_finalize_kernel<<<1, 256>>>(gamma, beta, l);
        bn_apply_kernel<<<(NN * 8 + 255) / 256, 256>>>(batch, l == LL - 1 ? 1 : 0);
    }

    classifier_kernel<<<(GG + 127) / 128, 128>>>(W_cls, b_cls, out);
}